// round 12
// baseline (speedup 1.0000x reference)
#include <cuda_runtime.h>
#include <cuda_fp16.h>
#include <stdint.h>

// OpticalConvolution: 3x3 conv pad1 stride1, B=16 Cin=128 H=W=56 Cout=256, fp32.
//
// Round 12: fp16 2-term HMMA, k' = r*128 + ci reorder (uniform tap per stage),
// CTA = M128 x N128 (2 batches), 8 warps as 2Mx4N with 64x32 warp tiles
// (LDSM/MMA ratio 0.25), double-buffered 96KB smem, 2 CTAs/SM.

#define CIN   128
#define COUT  256
#define HH    56
#define WW    56
#define HW    (HH * WW)
#define KTOT  1152
#define KSTAGE 64
#define NSTAGES 18
#define NIN   (16 * 128 * 56 * 56)

#define A_SZ 16384                 // 128 rows x 128B (fp16 hi)
#define B_SZ 16384                 // 128 rows x 128B per plane
#define A_HI 0
#define B_HI (A_SZ)
#define B_LO (A_SZ + B_SZ)
#define BUFSZ (A_SZ + 2 * B_SZ)          // 49152
#define SMEM_TOTAL (2 * BUFSZ)           // 98304

#define SWZ(x) ((x) ^ (((x) >> 3) & 0x70))

__device__ __align__(16) uint8_t W_img[2][NSTAGES][A_SZ];   // fp16 hi, k'-order, swizzled
__device__ uint32_t IN_pk[NIN];                              // f16hi<<16 | f16lo

__device__ __forceinline__ uint32_t s2u(const void* p) {
    uint32_t a;
    asm("{.reg .u64 t; cvta.to.shared.u64 t, %1; cvt.u32.u64 %0, t;}" : "=r"(a) : "l"(p));
    return a;
}

__device__ __forceinline__ void mma_f16(float* d, const uint32_t* a, const uint32_t* b) {
    asm volatile(
        "mma.sync.aligned.m16n8k16.row.col.f32.f16.f16.f32 "
        "{%0,%1,%2,%3}, {%4,%5,%6,%7}, {%8,%9}, {%0,%1,%2,%3};"
        : "+f"(d[0]), "+f"(d[1]), "+f"(d[2]), "+f"(d[3])
        : "r"(a[0]), "r"(a[1]), "r"(a[2]), "r"(a[3]), "r"(b[0]), "r"(b[1]));
}

#define LDSM4(r, a) \
    asm volatile("ldmatrix.sync.aligned.m8n8.x4.shared.b16 {%0,%1,%2,%3}, [%4];" \
                 : "=r"((r)[0]), "=r"((r)[1]), "=r"((r)[2]), "=r"((r)[3]) : "r"(a))

// ---------------- prep: pack input, pre-stage fp16 weights in k'-order ----------------
__global__ void prep_kernel(const float* __restrict__ in, const float* __restrict__ wt)
{
    const int tid = blockIdx.x * blockDim.x + threadIdx.x;
    const int nth = gridDim.x * blockDim.x;

    for (int i = tid; i < NIN; i += nth) {
        float v = in[i];
        __half h = __float2half_rn(v);
        float r = v - __half2float(h);
        __half l = __float2half_rn(r);
        IN_pk[i] = ((uint32_t)__half_as_ushort(h) << 16) | (uint32_t)__half_as_ushort(l);
    }

    const int WTOT = 2 * NSTAGES * 128 * 32;
    for (int i = tid; i < WTOT; i += nth) {
        int cb  = i / (NSTAGES * 128 * 32);
        int rem = i - cb * (NSTAGES * 128 * 32);
        int s   = rem >> 12;
        int row = (rem >> 5) & 127;
        int j   = rem & 31;
        int r   = s >> 1;                  // filter tap 0..8
        int ci0 = (s & 1) * 64 + 2 * j;    // channel pair
        const float* p = wt + (size_t)(cb * 128 + row) * KTOT;
        uint32_t h0 = __half_as_ushort(__float2half_rn(p[ci0 * 9 + r]));
        uint32_t h1 = __half_as_ushort(__float2half_rn(p[(ci0 + 1) * 9 + r]));
        uint32_t off = SWZ((uint32_t)row * 128 + j * 4);
        *(uint32_t*)&W_img[cb][s][off] = (h1 << 16) | h0;   // even k' in low half
    }
}

// ---------------- main GEMM kernel: M=128 x N=128 per CTA ----------------
__global__ __launch_bounds__(256, 2)
void conv_mma(const float* __restrict__ bias, float* __restrict__ out)
{
    extern __shared__ __align__(1024) char smem[];
    const uint32_t sb = s2u(smem);
    const int t = threadIdx.x;
    const int wid = t >> 5;
    const int lane = t & 31;

    const int tileId = blockIdx.x;          // 0..48
    const int ty = tileId / 7, tx = tileId % 7;
    const int y0 = ty * 8, x0 = tx * 8;
    const int cb = blockIdx.y;
    const int co0 = cb * 128;
    const int bz = blockIdx.z;              // batches bz*2, bz*2+1

    // ---- B-staging constants: thread <-> n-row (128), half <-> 16 k-pairs ----
    const int nB = t & 127;
    const int q16 = t >> 7;                 // 0..1
    const int b2 = nB >> 6;
    const int yy = (nB & 63) >> 3, xx = nB & 7;
    const int jxor = yy & 3;
    const uint32_t* ipk = IN_pk + (size_t)(bz * 2 + b2) * (CIN * HW);
    const int oy = y0 + yy - 1, ox = x0 + xx - 1;
    const uint32_t rowByteB = (uint32_t)nB * 128;

    // ---- warp tiling: 2 (M) x 4 (N); warp tile 64 x 32 ----
    const int mrow = (wid & 1) * 64;
    const int ncol = (wid >> 1) * 32;
    const int g = lane >> 2;
    const int c = lane & 3;

    // ---- ldmatrix per-lane address components ----
    const int arow = lane & 15;
    const uint32_t akoff = (uint32_t)(lane >> 4) << 4;
    const uint32_t xrA = (uint32_t)(arow & 7) << 4;
    uint32_t rbA[4];
    #pragma unroll
    for (int mt = 0; mt < 4; mt++)
        rbA[mt] = (uint32_t)(mrow + mt * 16 + arow) * 128;
    const int brow = (lane & 7) | ((lane >> 4) << 3);
    const uint32_t bkoff = (uint32_t)((lane >> 3) & 1) << 4;
    const uint32_t xrB = (uint32_t)(brow & 7) << 4;
    uint32_t rbB[2];
    rbB[0] = (uint32_t)(ncol + brow) * 128;
    rbB[1] = (uint32_t)(ncol + 16 + brow) * 128;

    float acc[4][4][4];                     // [mt][nt][frag]
    #pragma unroll
    for (int mt = 0; mt < 4; mt++)
        #pragma unroll
        for (int nt = 0; nt < 4; nt++)
            #pragma unroll
            for (int r = 0; r < 4; r++) acc[mt][nt][r] = 0.0f;

    auto stageA = [&](int s, int buf) {
        const uint8_t* ws = &W_img[cb][s][0];
        uint32_t dst = sb + buf * BUFSZ + A_HI;
        #pragma unroll
        for (int it = 0; it < 4; it++) {
            uint32_t off = it * 4096 + t * 16;
            asm volatile("cp.async.cg.shared.global [%0], [%1], 16;"
                         :: "r"(dst + off), "l"(ws + off) : "memory");
        }
    };
    auto stageB = [&](int s, int buf) {
        int r  = s >> 1;
        int ky = (r >= 6) ? 2 : (r >= 3 ? 1 : 0);
        int kx = r - ky * 3;
        int iy = oy + ky, ix = ox + kx;
        bool valid = ((unsigned)iy < HH) && ((unsigned)ix < WW);
        const uint32_t* src = ipk + (s & 1) * 64 * HW + iy * WW + ix;
        char* bufp = smem + (size_t)buf * BUFSZ;
        #pragma unroll
        for (int jj = 0; jj < 16; jj++) {
            int j = (q16 * 16 + jj) ^ jxor;
            uint32_t a0 = 0, a1 = 0;
            if (valid) {
                a0 = src[2 * j * HW];
                a1 = src[(2 * j + 1) * HW];
            }
            uint32_t hi, lo;
            asm("prmt.b32 %0, %1, %2, 0x7632;" : "=r"(hi) : "r"(a0), "r"(a1));
            asm("prmt.b32 %0, %1, %2, 0x5410;" : "=r"(lo) : "r"(a0), "r"(a1));
            uint32_t off = SWZ(rowByteB + (uint32_t)j * 4);
            *(uint32_t*)(bufp + B_HI + off) = hi;
            *(uint32_t*)(bufp + B_LO + off) = lo;
        }
    };

    // ---- prologue ----
    stageA(0, 0);
    asm volatile("cp.async.commit_group;" ::: "memory");
    stageB(0, 0);

    for (int s = 0; s < NSTAGES; s++) {
        asm volatile("cp.async.wait_group 0;" ::: "memory");
        __syncthreads();
        if (s + 1 < NSTAGES) {
            stageA(s + 1, (s + 1) & 1);
            asm volatile("cp.async.commit_group;" ::: "memory");
            stageB(s + 1, (s + 1) & 1);
        }

        const uint32_t cu = sb + (uint32_t)(s & 1) * BUFSZ;
        #pragma unroll
        for (int q = 0; q < 4; q++) {
            const uint32_t kA = (uint32_t)(q * 32) + akoff;
            const uint32_t kB = (uint32_t)(q * 32) + bkoff;
            uint32_t ah[4][4], bb[2][4];
            // A fragments (4) + B-hi fragments (2)
            #pragma unroll
            for (int mt = 0; mt < 4; mt++)
                LDSM4(ah[mt], cu + rbA[mt] + (kA ^ xrA) + A_HI);
            #pragma unroll
            for (int np = 0; np < 2; np++)
                LDSM4(bb[np], cu + rbB[np] + (kB ^ xrB) + B_HI);
            // hi term: 16 distinct-acc MMAs
            #pragma unroll
            for (int mt = 0; mt < 4; mt++)
                #pragma unroll
                for (int np = 0; np < 2; np++) {
                    mma_f16(acc[mt][2 * np],     ah[mt], &bb[np][0]);
                    mma_f16(acc[mt][2 * np + 1], ah[mt], &bb[np][2]);
                }
            // B-lo fragments overwrite bb, then lo term
            #pragma unroll
            for (int np = 0; np < 2; np++)
                LDSM4(bb[np], cu + rbB[np] + (kB ^ xrB) + B_LO);
            #pragma unroll
            for (int mt = 0; mt < 4; mt++)
                #pragma unroll
                for (int np = 0; np < 2; np++) {
                    mma_f16(acc[mt][2 * np],     ah[mt], &bb[np][0]);
                    mma_f16(acc[mt][2 * np + 1], ah[mt], &bb[np][2]);
                }
        }
    }

    // ---- epilogue: bias + direct float2 stores ----
    #pragma unroll
    for (int mt = 0; mt < 4; mt++) {
        int coA = co0 + mrow + mt * 16 + g;
        int coB = coA + 8;
        float bvA = __ldg(&bias[coA]);
        float bvB = __ldg(&bias[coB]);
        #pragma unroll
        for (int nt = 0; nt < 4; nt++) {
            int n0 = ncol + nt * 8 + c * 2;       // 0..127
            int bb2 = bz * 2 + (n0 >> 6);
            int yq = (n0 >> 3) & 7;
            int xq = n0 & 7;
            float* gA = out + (((size_t)bb2 * COUT + coA) * HH + (y0 + yq)) * WW + x0 + xq;
            float* gB = out + (((size_t)bb2 * COUT + coB) * HH + (y0 + yq)) * WW + x0 + xq;
            *(float2*)gA = make_float2(acc[mt][nt][0] + bvA, acc[mt][nt][1] + bvA);
            *(float2*)gB = make_float2(acc[mt][nt][2] + bvB, acc[mt][nt][3] + bvB);
        }
    }
}

extern "C" void kernel_launch(void* const* d_in, const int* in_sizes, int n_in,
                              void* d_out, int out_size)
{
    const float* tensor  = (const float*)d_in[0];   // [16,128,56,56]
    const float* weights = (const float*)d_in[1];   // [256,128,3,3]
    const float* bias    = (const float*)d_in[2];   // [256]
    float* out = (float*)d_out;                     // [16,256,56,56]

    prep_kernel<<<2048, 256>>>(tensor, weights);

    cudaFuncSetAttribute(conv_mma,
                         cudaFuncAttributeMaxDynamicSharedMemorySize, SMEM_TOTAL);
    dim3 grid(49, 2, 8);
    conv_mma<<<grid, 256, SMEM_TOTAL>>>(bias, out);
}